// round 13
// baseline (speedup 1.0000x reference)
#include <cuda_runtime.h>
#include <cuda_fp16.h>
#include <cuda_bf16.h>
#include <cstdint>

#define NNODE 100000
#define DDIM  256
#define EMAX  3400000

// ---------------- scratch (static device globals; no allocation) -------------
__device__ __half g_h2h  [(size_t)NNODE * DDIM];  // h @ W (fp16, gather source)
__device__ __half g_hmidh[(size_t)NNODE * DDIM];  // layer-1 output (fp16)
__device__ float  g_ssrc[NNODE];
__device__ float  g_sdst[NNODE];
__device__ int    g_counts[NNODE];
__device__ int    g_rowptr[NNODE + 1];
__device__ int    g_cursor[NNODE];
__device__ int    g_col[EMAX];
__device__ int    g_bsum[64];
__device__ int    g_boff[64];
// W^T as fp16, per layer: [N=256][K=256]
__device__ __half g_W1h[65536];
__device__ __half g_W2h[65536];

// ---------------- helpers -----------------------------------------------------
__device__ __forceinline__ uint32_t smem_u32(const void* p) {
    uint32_t a;
    asm("{ .reg .u64 t; cvta.to.shared.u64 t, %1; cvt.u32.u64 %0, t; }" : "=r"(a) : "l"(p));
    return a;
}
__device__ __forceinline__ void cpasync16(uint32_t dst, const void* src) {
    asm volatile("cp.async.cg.shared.global [%0], [%1], 16;" :: "r"(dst), "l"(src));
}
#define CP_COMMIT() asm volatile("cp.async.commit_group;")
#define CP_WAIT0()  asm volatile("cp.async.wait_group 0;")
#define LDSM4(R, addr) \
    asm volatile("ldmatrix.sync.aligned.m8n8.x4.shared.b16 {%0,%1,%2,%3}, [%4];" \
                 : "=r"((R)[0]), "=r"((R)[1]), "=r"((R)[2]), "=r"((R)[3]) : "r"(addr))

__device__ __forceinline__ void mma_f16(float* c, const uint32_t* a,
                                        uint32_t b0, uint32_t b1) {
    asm volatile(
        "mma.sync.aligned.m16n8k16.row.col.f32.f16.f16.f32 "
        "{%0,%1,%2,%3}, {%4,%5,%6,%7}, {%8,%9}, {%0,%1,%2,%3};"
        : "+f"(c[0]), "+f"(c[1]), "+f"(c[2]), "+f"(c[3])
        : "r"(a[0]), "r"(a[1]), "r"(a[2]), "r"(a[3]), "r"(b0), "r"(b1));
}

// ---------------- CSR build --------------------------------------------------
__global__ void zero_counts_k(int n) {
    int i = blockIdx.x * blockDim.x + threadIdx.x;
    if (i < n) g_counts[i] = 0;
}

__global__ void hist_k(const int* __restrict__ src, int E) {
    int i = (blockIdx.x * blockDim.x + threadIdx.x) * 4;
    if (i + 3 < E) {
        int4 s = *(const int4*)(src + i);
        atomicAdd(&g_counts[s.x], 1);
        atomicAdd(&g_counts[s.y], 1);
        atomicAdd(&g_counts[s.z], 1);
        atomicAdd(&g_counts[s.w], 1);
    } else {
        for (int q = i; q < E; q++) atomicAdd(&g_counts[src[q]], 1);
    }
}

__global__ void scan1_k(int n) {
    __shared__ int wsum[32];
    const int tid = threadIdx.x, lane = tid & 31, w = tid >> 5;
    const int i0 = blockIdx.x * 4096 + tid * 4;
    int v0 = 0, v1 = 0, v2 = 0, v3 = 0;
    if (i0 + 3 < n) {
        int4 t = *(const int4*)&g_counts[i0];
        v0 = t.x; v1 = t.y; v2 = t.z; v3 = t.w;
    } else {
        if (i0 + 0 < n) v0 = g_counts[i0 + 0];
        if (i0 + 1 < n) v1 = g_counts[i0 + 1];
        if (i0 + 2 < n) v2 = g_counts[i0 + 2];
        if (i0 + 3 < n) v3 = g_counts[i0 + 3];
    }
    int s0 = v0, s1 = s0 + v1, s2 = s1 + v2, s3 = s2 + v3;
    int incl = s3;
    #pragma unroll
    for (int off = 1; off < 32; off <<= 1) {
        int u = __shfl_up_sync(0xffffffffu, incl, off);
        if (lane >= off) incl += u;
    }
    if (lane == 31) wsum[w] = incl;
    __syncthreads();
    if (w == 0) {
        int x = wsum[lane], xi = x;
        #pragma unroll
        for (int off = 1; off < 32; off <<= 1) {
            int u = __shfl_up_sync(0xffffffffu, xi, off);
            if (lane >= off) xi += u;
        }
        if (lane == 31) g_bsum[blockIdx.x] = xi;
        wsum[lane] = xi - x;
    }
    __syncthreads();
    int eb = wsum[w] + (incl - s3);
    if (i0 + 0 < n) g_rowptr[i0 + 0] = eb;
    if (i0 + 1 < n) g_rowptr[i0 + 1] = eb + s0;
    if (i0 + 2 < n) g_rowptr[i0 + 2] = eb + s1;
    if (i0 + 3 < n) g_rowptr[i0 + 3] = eb + s2;
}

__global__ void scan2_k(int nb, int n) {
    int lane = threadIdx.x;
    int v = (lane < nb) ? g_bsum[lane] : 0;
    int xi = v;
    #pragma unroll
    for (int off = 1; off < 32; off <<= 1) {
        int u = __shfl_up_sync(0xffffffffu, xi, off);
        if (lane >= off) xi += u;
    }
    if (lane < nb) g_boff[lane] = xi - v;
    if (lane == 31) g_rowptr[n] = xi;
}

__global__ void scan3_k(int n) {
    const int i0 = blockIdx.x * 4096 + threadIdx.x * 4;
    const int off = g_boff[blockIdx.x];
    #pragma unroll
    for (int q = 0; q < 4; q++) {
        int i = i0 + q;
        if (i < n) {
            int v = g_rowptr[i] + off;
            g_rowptr[i] = v;
            g_cursor[i] = v;
        }
    }
}

__global__ void scatter_k(const int* __restrict__ src, const int* __restrict__ dst, int E) {
    int i = (blockIdx.x * blockDim.x + threadIdx.x) * 4;
    if (i + 3 < E) {
        int4 s = *(const int4*)(src + i);
        int4 d = *(const int4*)(dst + i);
        g_col[atomicAdd(&g_cursor[s.x], 1)] = d.x;
        g_col[atomicAdd(&g_cursor[s.y], 1)] = d.y;
        g_col[atomicAdd(&g_cursor[s.z], 1)] = d.z;
        g_col[atomicAdd(&g_cursor[s.w], 1)] = d.w;
    } else {
        for (int q = i; q < E; q++)
            g_col[atomicAdd(&g_cursor[src[q]], 1)] = dst[q];
    }
}

// ---------------- W transpose to fp16 ----------------------------------------
__global__ void wsplit_k(const float* __restrict__ W, __half* __restrict__ Wh) {
    int n = blockIdx.x, k = threadIdx.x;
    Wh[n * 256 + k] = __float2half_rn(W[k * 256 + n]);
}

// ---------------- HMMA fp16 GEMM (single term) -------------------------------
// C[M,256] = A[M,256] @ W ; C = Ah*Bh, both fp16, fp32 accumulate.
// CTA 128x256, 8 warps (2m x 4n), warp tile 64x64, K chunk 32, double-buffered.
// Epilogue: fp16 C store + score projections reduced in smem.
#define STRIDE  80
#define B_H_OFF 10240
#define STAGE_B 30720
#define GSMEM_B (2 * STAGE_B)

template <int AF32>
__global__ __launch_bounds__(256, 1) void mmagemm_k(const void* __restrict__ Av,
                                                    const __half* __restrict__ Bh,
                                                    const float* __restrict__ avec,
                                                    __half* __restrict__ Chalf, int M) {
    extern __shared__ char smem[];
    const uint32_t sbase = smem_u32(smem);
    const int tid = threadIdx.x;
    const int rowBlock = blockIdx.x * 128;
    const int wid = tid >> 5, lane = tid & 31;
    const int warpRow = (wid >> 2) * 64;
    const int warpCol = (wid & 3) * 64;
    const int qrow = lane >> 2, qcol = lane & 3;

    float acc[4][8][4];
    #pragma unroll
    for (int i = 0; i < 4; i++)
        #pragma unroll
        for (int j = 0; j < 8; j++)
            #pragma unroll
            for (int t = 0; t < 4; t++) acc[i][j][t] = 0.f;

    const int ldRow = tid >> 1, ldHalf = tid & 1;
    const int aRowG = rowBlock + ldRow;
    float fA[16];

    auto loadA = [&](int kc) {
        if constexpr (AF32) {
            const float* A = (const float*)Av;
            if (aRowG < M) {
                const float4* ap = (const float4*)(A + (size_t)aRowG * 256 + kc * 32 + ldHalf * 16);
                #pragma unroll
                for (int q = 0; q < 4; q++) *(float4*)&fA[q * 4] = __ldcs(ap + q);
            } else {
                #pragma unroll
                for (int q = 0; q < 16; q++) fA[q] = 0.f;
            }
        }
    };
    auto storeA = [&](int s) {
        if constexpr (AF32) {
            char* st = smem + s * STAGE_B;
            uint32_t hp[8];
            #pragma unroll
            for (int j = 0; j < 8; j++) {
                __half2 h = __floats2half2_rn(fA[2 * j], fA[2 * j + 1]);
                hp[j] = *(uint32_t*)&h;
            }
            const int off = ldRow * STRIDE + ldHalf * 32;
            *(uint4*)(st + off)      = *(uint4*)&hp[0];
            *(uint4*)(st + off + 16) = *(uint4*)&hp[4];
        }
    };
    auto loadB = [&](int kc, int s) {
        const uint32_t sdst = sbase + s * STAGE_B + B_H_OFF;
        #pragma unroll
        for (int u = 0; u < 4; u++) {
            int idx = tid + u * 256;          // 0..1023
            int row = idx >> 2, q = idx & 3;
            const __half* srcp = Bh + (size_t)row * 256 + kc * 32 + q * 8;
            cpasync16(sdst + row * STRIDE + q * 16, srcp);
        }
        if constexpr (!AF32) {
            const __half* A = (const __half*)Av;
            const uint32_t adst = sbase + s * STAGE_B;
            #pragma unroll
            for (int u = 0; u < 2; u++) {
                int idx = tid + u * 256;      // 0..511
                int row = idx >> 2, q = idx & 3;
                int grow = rowBlock + row;
                const __half* srcp = A + (size_t)(grow < M ? grow : M - 1) * 256 + kc * 32 + q * 8;
                cpasync16(adst + row * STRIDE + q * 16, srcp);
            }
        }
        CP_COMMIT();
    };

    // prologue
    loadA(0);
    loadB(0, 0);
    storeA(0);

    for (int kc = 0; kc < 8; kc++) {
        const int cur = kc & 1;
        CP_WAIT0();
        __syncthreads();
        if (kc < 7) { loadA(kc + 1); loadB(kc + 1, cur ^ 1); }

        const uint32_t sA = sbase + cur * STAGE_B;
        const uint32_t sB = sA + B_H_OFF;

        #pragma unroll
        for (int ks = 0; ks < 2; ks++) {
            uint32_t ah[4][4];
            const uint32_t arow = ((lane >> 3) & 1) * 8 + (lane & 7);
            const uint32_t akb  = ks * 32 + (lane >> 4) * 16;
            #pragma unroll
            for (int i = 0; i < 4; i++) {
                uint32_t addr = sA + (warpRow + i * 16 + arow) * STRIDE + akb;
                LDSM4(ah[i], addr);
            }
            const uint32_t brow = (lane >> 4) * 8 + (lane & 7);
            const uint32_t bkb  = ks * 32 + ((lane >> 3) & 1) * 16;
            #pragma unroll
            for (int jj = 0; jj < 4; jj++) {
                uint32_t bh[4];
                uint32_t addr = sB + (warpCol + jj * 16 + brow) * STRIDE + bkb;
                LDSM4(bh, addr);
                #pragma unroll
                for (int i = 0; i < 4; i++) {
                    mma_f16(acc[i][jj * 2],     ah[i], bh[0], bh[1]);
                    mma_f16(acc[i][jj * 2 + 1], ah[i], bh[2], bh[3]);
                }
            }
        }
        if (kc < 7) storeA(cur ^ 1);
    }

    // ---- epilogue: fp16 store + score projections via smem reduction ----
    __syncthreads();
    float* sS1 = (float*)smem;          // [128]
    float* sS2 = (float*)smem + 128;    // [128]
    if (tid < 128) { sS1[tid] = 0.f; sS2[tid] = 0.f; }
    __syncthreads();

    float a1x[8], a1y[8], a2x[8], a2y[8];
    #pragma unroll
    for (int j = 0; j < 8; j++) {
        const int c0 = warpCol + j * 8 + 2 * qcol;
        float2 p1 = *(const float2*)(avec + c0);
        float2 p2 = *(const float2*)(avec + 256 + c0);
        a1x[j] = p1.x; a1y[j] = p1.y;
        a2x[j] = p2.x; a2y[j] = p2.y;
    }
    #pragma unroll
    for (int i = 0; i < 4; i++) {
        const int lr0 = warpRow + i * 16 + qrow;
        const int lr1 = lr0 + 8;
        const int r0 = rowBlock + lr0, r1 = rowBlock + lr1;
        float s1_0 = 0.f, s2_0 = 0.f, s1_1 = 0.f, s2_1 = 0.f;
        #pragma unroll
        for (int j = 0; j < 8; j++) {
            const int c0 = warpCol + j * 8 + 2 * qcol;
            s1_0 += acc[i][j][0] * a1x[j] + acc[i][j][1] * a1y[j];
            s2_0 += acc[i][j][0] * a2x[j] + acc[i][j][1] * a2y[j];
            s1_1 += acc[i][j][2] * a1x[j] + acc[i][j][3] * a1y[j];
            s2_1 += acc[i][j][2] * a2x[j] + acc[i][j][3] * a2y[j];
            if (r0 < M) {
                __half2 h = __floats2half2_rn(acc[i][j][0], acc[i][j][1]);
                *(__half2*)(Chalf + (size_t)r0 * 256 + c0) = h;
            }
            if (r1 < M) {
                __half2 h = __floats2half2_rn(acc[i][j][2], acc[i][j][3]);
                *(__half2*)(Chalf + (size_t)r1 * 256 + c0) = h;
            }
        }
        #pragma unroll
        for (int off = 1; off < 4; off <<= 1) {
            s1_0 += __shfl_xor_sync(0xffffffffu, s1_0, off);
            s2_0 += __shfl_xor_sync(0xffffffffu, s2_0, off);
            s1_1 += __shfl_xor_sync(0xffffffffu, s1_1, off);
            s2_1 += __shfl_xor_sync(0xffffffffu, s2_1, off);
        }
        if (qcol == 0) {
            atomicAdd(&sS1[lr0], s1_0);
            atomicAdd(&sS2[lr0], s2_0);
            atomicAdd(&sS1[lr1], s1_1);
            atomicAdd(&sS2[lr1], s2_1);
        }
    }
    __syncthreads();
    if (tid < 128 && rowBlock + tid < M) {
        g_ssrc[rowBlock + tid] = sS1[tid];
        g_sdst[rowBlock + tid] = sS2[tid];
    }
}

// ---------------- edge aggregation: one warp per node, fp16 gather -----------
__device__ __forceinline__ float elu1(float x) {
    return x > 0.f ? x : (__expf(x) - 1.f);
}

template <typename OT>
__global__ __launch_bounds__(256) void agg_k(const __half* __restrict__ h2h,
                                             OT* __restrict__ out, int n) {
    int warp = (blockIdx.x * blockDim.x + threadIdx.x) >> 5;
    int lane = threadIdx.x & 31;
    if (warp >= n) return;
    const int start = g_rowptr[warp];
    const int end   = g_rowptr[warp + 1];
    const float s_i = g_ssrc[warp];

    float acc[8];
    #pragma unroll
    for (int t = 0; t < 8; t++) acc[t] = 0.f;
    float denom = 0.f;

    for (int j = start; j < end; j += 32) {
        int myj = j + lane;
        float e = 0.f;
        int d = 0;
        if (myj < end) {
            d = g_col[myj];
            float sc = s_i + g_sdst[d];
            float l  = sc > 0.f ? sc : 0.2f * sc;
            e = __expf(-l);
        }
        int cnt = end - j;
        if (cnt > 32) cnt = 32;
        #pragma unroll 4
        for (int k = 0; k < cnt; k++) {
            float ek = __shfl_sync(0xffffffffu, e, k);
            int   dk = __shfl_sync(0xffffffffu, d, k);
            uint4 v = ((const uint4*)(h2h + (size_t)dk * 256))[lane];
            float2 f0 = __half22float2(*(__half2*)&v.x);
            float2 f1 = __half22float2(*(__half2*)&v.y);
            float2 f2 = __half22float2(*(__half2*)&v.z);
            float2 f3 = __half22float2(*(__half2*)&v.w);
            acc[0] += ek * f0.x; acc[1] += ek * f0.y;
            acc[2] += ek * f1.x; acc[3] += ek * f1.y;
            acc[4] += ek * f2.x; acc[5] += ek * f2.y;
            acc[6] += ek * f3.x; acc[7] += ek * f3.y;
            denom += ek;
        }
    }
    float inv = denom > 0.f ? 1.0f / denom : 0.f;
    float o[8];
    #pragma unroll
    for (int t = 0; t < 8; t++) o[t] = elu1(acc[t] * inv);
    if constexpr (sizeof(OT) == 2) {
        uint4 hb;
        __half2 h0 = __floats2half2_rn(o[0], o[1]);
        __half2 h1 = __floats2half2_rn(o[2], o[3]);
        __half2 h2 = __floats2half2_rn(o[4], o[5]);
        __half2 h3 = __floats2half2_rn(o[6], o[7]);
        hb.x = *(uint32_t*)&h0; hb.y = *(uint32_t*)&h1;
        hb.z = *(uint32_t*)&h2; hb.w = *(uint32_t*)&h3;
        __stcs((uint4*)((__half*)out + (size_t)warp * 256 + lane * 8), hb);
    } else {
        float4* orow = (float4*)((float*)out + (size_t)warp * 256 + lane * 8);
        __stcs(orow,     *(float4*)&o[0]);
        __stcs(orow + 1, *(float4*)&o[4]);
    }
}

// ---------------- launch -----------------------------------------------------
extern "C" void kernel_launch(void* const* d_in, const int* in_sizes, int n_in,
                              void* d_out, int out_size) {
    const float* emb  = (const float*)d_in[0];
    const float* W1   = (const float*)d_in[1];
    const float* a1   = (const float*)d_in[2];
    const float* W2   = (const float*)d_in[3];
    const float* a2   = (const float*)d_in[4];
    const int*   edges = (const int*)d_in[5];

    const int N = in_sizes[0] / DDIM;     // 100000
    const int E = in_sizes[5] / 2;        // 3300000
    const int* src = edges;
    const int* dst = edges + E;

    __half* h2h;   cudaGetSymbolAddress((void**)&h2h,   g_h2h);
    __half* hmidh; cudaGetSymbolAddress((void**)&hmidh, g_hmidh);
    __half *w1h, *w2h;
    cudaGetSymbolAddress((void**)&w1h, g_W1h);
    cudaGetSymbolAddress((void**)&w2h, g_W2h);
    float* out = (float*)d_out;

    cudaFuncSetAttribute(mmagemm_k<1>, cudaFuncAttributeMaxDynamicSharedMemorySize, GSMEM_B);
    cudaFuncSetAttribute(mmagemm_k<0>, cudaFuncAttributeMaxDynamicSharedMemorySize, GSMEM_B);

    const int TB = 256;
    const int gemm_grid = (N + 127) / 128;
    const int e4 = (E / 4 + TB - 1) / TB + 1;
    const int nscan = (N + 4095) / 4096;

    // fork: CSR build + W2 prep on side stream; W1 prep + GEMM1 on main stream
    cudaStream_t s2;
    cudaEvent_t evFork, evJoin;
    cudaStreamCreateWithFlags(&s2, cudaStreamNonBlocking);
    cudaEventCreateWithFlags(&evFork, cudaEventDisableTiming);
    cudaEventCreateWithFlags(&evJoin, cudaEventDisableTiming);

    cudaEventRecord(evFork, 0);
    cudaStreamWaitEvent(s2, evFork, 0);

    // side stream: CSR build + W2 split (independent of GEMM1)
    zero_counts_k<<<(N + TB - 1) / TB, TB, 0, s2>>>(N);
    hist_k<<<e4, TB, 0, s2>>>(src, E);
    scan1_k<<<nscan, 1024, 0, s2>>>(N);
    scan2_k<<<1, 32, 0, s2>>>(nscan, N);
    scan3_k<<<nscan, 1024, 0, s2>>>(N);
    scatter_k<<<e4, TB, 0, s2>>>(src, dst, E);
    wsplit_k<<<256, 256, 0, s2>>>(W2, w2h);
    cudaEventRecord(evJoin, s2);

    // main stream: W1 prep + layer-1 GEMM
    wsplit_k<<<256, 256>>>(W1, w1h);
    mmagemm_k<1><<<gemm_grid, TB, GSMEM_B>>>(emb, w1h, a1, h2h, N);

    // join: aggregation needs CSR + GEMM1
    cudaStreamWaitEvent(0, evJoin, 0);
    agg_k<__half><<<(N * 32 + TB - 1) / TB, TB>>>(h2h, hmidh, N);

    // layer 2 (A already fp16; W2 split done on side stream before join)
    mmagemm_k<0><<<gemm_grid, TB, GSMEM_B>>>(hmidh, w2h, a2, h2h, N);
    agg_k<float><<<(N * 32 + TB - 1) / TB, TB>>>(h2h, out, N);
}

// round 16
// speedup vs baseline: 1.0177x; 1.0177x over previous
#include <cuda_runtime.h>
#include <cuda_fp16.h>
#include <cuda_bf16.h>
#include <cstdint>

#define NNODE 100000
#define DDIM  256
#define EMAX  3400000

// ---------------- scratch (static device globals; no allocation) -------------
__device__ __half g_h2h  [(size_t)NNODE * DDIM];  // h @ W (fp16, gather source)
__device__ __half g_hmidh[(size_t)NNODE * DDIM];  // layer-1 output (fp16)
__device__ float  g_ssrc[NNODE];
__device__ float  g_sdst[NNODE];
__device__ int    g_counts[NNODE];
__device__ int    g_rowptr[NNODE + 1];
__device__ int    g_rank[EMAX];
__device__ int    g_col[EMAX];
__device__ int    g_bsum[64];
// W^T as fp16, per layer: [N=256][K=256]
__device__ __half g_W1h[65536];
__device__ __half g_W2h[65536];

// ---------------- helpers -----------------------------------------------------
__device__ __forceinline__ uint32_t smem_u32(const void* p) {
    uint32_t a;
    asm("{ .reg .u64 t; cvta.to.shared.u64 t, %1; cvt.u32.u64 %0, t; }" : "=r"(a) : "l"(p));
    return a;
}
__device__ __forceinline__ void cpasync16(uint32_t dst, const void* src) {
    asm volatile("cp.async.cg.shared.global [%0], [%1], 16;" :: "r"(dst), "l"(src));
}
#define CP_COMMIT() asm volatile("cp.async.commit_group;")
#define CP_WAIT0()  asm volatile("cp.async.wait_group 0;")
#define LDSM4(R, addr) \
    asm volatile("ldmatrix.sync.aligned.m8n8.x4.shared.b16 {%0,%1,%2,%3}, [%4];" \
                 : "=r"((R)[0]), "=r"((R)[1]), "=r"((R)[2]), "=r"((R)[3]) : "r"(addr))

__device__ __forceinline__ void mma_f16(float* c, const uint32_t* a,
                                        uint32_t b0, uint32_t b1) {
    asm volatile(
        "mma.sync.aligned.m16n8k16.row.col.f32.f16.f16.f32 "
        "{%0,%1,%2,%3}, {%4,%5,%6,%7}, {%8,%9}, {%0,%1,%2,%3};"
        : "+f"(c[0]), "+f"(c[1]), "+f"(c[2]), "+f"(c[3])
        : "r"(a[0]), "r"(a[1]), "r"(a[2]), "r"(a[3]), "r"(b0), "r"(b1));
}

// ---------------- CSR build --------------------------------------------------
__global__ void zero_counts_k(int n) {
    int i = blockIdx.x * blockDim.x + threadIdx.x;
    if (i < n) g_counts[i] = 0;
}

// histogram + per-edge rank (old count value)
__global__ void hist_k(const int* __restrict__ src, int E) {
    int i = (blockIdx.x * blockDim.x + threadIdx.x) * 4;
    if (i + 3 < E) {
        int4 s = *(const int4*)(src + i);
        int4 r;
        r.x = atomicAdd(&g_counts[s.x], 1);
        r.y = atomicAdd(&g_counts[s.y], 1);
        r.z = atomicAdd(&g_counts[s.z], 1);
        r.w = atomicAdd(&g_counts[s.w], 1);
        *(int4*)(g_rank + i) = r;
    } else {
        for (int q = i; q < E; q++) g_rank[q] = atomicAdd(&g_counts[src[q]], 1);
    }
}

// phase 1: per-block (4096 elems) exclusive scan into rowptr + block sums
__global__ void scan1_k(int n) {
    __shared__ int wsum[32];
    const int tid = threadIdx.x, lane = tid & 31, w = tid >> 5;
    const int i0 = blockIdx.x * 4096 + tid * 4;
    int v0 = 0, v1 = 0, v2 = 0, v3 = 0;
    if (i0 + 3 < n) {
        int4 t = *(const int4*)&g_counts[i0];
        v0 = t.x; v1 = t.y; v2 = t.z; v3 = t.w;
    } else {
        if (i0 + 0 < n) v0 = g_counts[i0 + 0];
        if (i0 + 1 < n) v1 = g_counts[i0 + 1];
        if (i0 + 2 < n) v2 = g_counts[i0 + 2];
        if (i0 + 3 < n) v3 = g_counts[i0 + 3];
    }
    int s0 = v0, s1 = s0 + v1, s2 = s1 + v2, s3 = s2 + v3;
    int incl = s3;
    #pragma unroll
    for (int off = 1; off < 32; off <<= 1) {
        int u = __shfl_up_sync(0xffffffffu, incl, off);
        if (lane >= off) incl += u;
    }
    if (lane == 31) wsum[w] = incl;
    __syncthreads();
    if (w == 0) {
        int x = wsum[lane], xi = x;
        #pragma unroll
        for (int off = 1; off < 32; off <<= 1) {
            int u = __shfl_up_sync(0xffffffffu, xi, off);
            if (lane >= off) xi += u;
        }
        if (lane == 31) g_bsum[blockIdx.x] = xi;
        wsum[lane] = xi - x;
    }
    __syncthreads();
    int eb = wsum[w] + (incl - s3);
    if (i0 + 0 < n) g_rowptr[i0 + 0] = eb;
    if (i0 + 1 < n) g_rowptr[i0 + 1] = eb + s0;
    if (i0 + 2 < n) g_rowptr[i0 + 2] = eb + s1;
    if (i0 + 3 < n) g_rowptr[i0 + 3] = eb + s2;
}

// phase 2: every block redundantly scans the <=32 block sums, adds its offset
__global__ void scanfix_k(int n, int nb) {
    __shared__ int soff[2];
    if (threadIdx.x < 32) {
        int lane = threadIdx.x;
        int v = (lane < nb) ? g_bsum[lane] : 0;
        int xi = v;
        #pragma unroll
        for (int off = 1; off < 32; off <<= 1) {
            int u = __shfl_up_sync(0xffffffffu, xi, off);
            if (lane >= off) xi += u;
        }
        if (lane == (int)blockIdx.x) soff[0] = xi - v;   // exclusive prefix of this block
        if (lane == nb - 1)          soff[1] = xi;       // grand total
    }
    __syncthreads();
    const int off = soff[0];
    const int i0 = blockIdx.x * 4096 + threadIdx.x * 4;
    #pragma unroll
    for (int q = 0; q < 4; q++) {
        int i = i0 + q;
        if (i < n) g_rowptr[i] += off;
    }
    if ((int)blockIdx.x == nb - 1 && threadIdx.x == 0) g_rowptr[n] = soff[1];
}

// atomic-free scatter: position = rowptr[src] + rank
__global__ void scatter_k(const int* __restrict__ src, const int* __restrict__ dst, int E) {
    int i = (blockIdx.x * blockDim.x + threadIdx.x) * 4;
    if (i + 3 < E) {
        int4 s = *(const int4*)(src + i);
        int4 d = *(const int4*)(dst + i);
        int4 r = *(const int4*)(g_rank + i);
        g_col[g_rowptr[s.x] + r.x] = d.x;
        g_col[g_rowptr[s.y] + r.y] = d.y;
        g_col[g_rowptr[s.z] + r.z] = d.z;
        g_col[g_rowptr[s.w] + r.w] = d.w;
    } else {
        for (int q = i; q < E; q++)
            g_col[g_rowptr[src[q]] + g_rank[q]] = dst[q];
    }
}

// ---------------- W transpose to fp16 ----------------------------------------
__global__ void wsplit_k(const float* __restrict__ W, __half* __restrict__ Wh) {
    int n = blockIdx.x, k = threadIdx.x;
    Wh[n * 256 + k] = __float2half_rn(W[k * 256 + n]);
}

// ---------------- HMMA fp16 GEMM (single term) -------------------------------
// C[M,256] = A[M,256] @ W ; C = Ah*Bh, both fp16, fp32 accumulate.
// CTA 128x256, 8 warps (2m x 4n), warp tile 64x64, K chunk 32, double-buffered.
// Epilogue: fp16 C store + score projections reduced in smem.
#define STRIDE  80
#define B_H_OFF 10240
#define STAGE_B 30720
#define GSMEM_B (2 * STAGE_B)

template <int AF32>
__global__ __launch_bounds__(256, 1) void mmagemm_k(const void* __restrict__ Av,
                                                    const __half* __restrict__ Bh,
                                                    const float* __restrict__ avec,
                                                    __half* __restrict__ Chalf, int M) {
    extern __shared__ char smem[];
    const uint32_t sbase = smem_u32(smem);
    const int tid = threadIdx.x;
    const int rowBlock = blockIdx.x * 128;
    const int wid = tid >> 5, lane = tid & 31;
    const int warpRow = (wid >> 2) * 64;
    const int warpCol = (wid & 3) * 64;
    const int qrow = lane >> 2, qcol = lane & 3;

    float acc[4][8][4];
    #pragma unroll
    for (int i = 0; i < 4; i++)
        #pragma unroll
        for (int j = 0; j < 8; j++)
            #pragma unroll
            for (int t = 0; t < 4; t++) acc[i][j][t] = 0.f;

    const int ldRow = tid >> 1, ldHalf = tid & 1;
    const int aRowG = rowBlock + ldRow;
    float fA[16];

    auto loadA = [&](int kc) {
        if constexpr (AF32) {
            const float* A = (const float*)Av;
            if (aRowG < M) {
                const float4* ap = (const float4*)(A + (size_t)aRowG * 256 + kc * 32 + ldHalf * 16);
                #pragma unroll
                for (int q = 0; q < 4; q++) *(float4*)&fA[q * 4] = ap[q];
            } else {
                #pragma unroll
                for (int q = 0; q < 16; q++) fA[q] = 0.f;
            }
        }
    };
    auto storeA = [&](int s) {
        if constexpr (AF32) {
            char* st = smem + s * STAGE_B;
            uint32_t hp[8];
            #pragma unroll
            for (int j = 0; j < 8; j++) {
                __half2 h = __floats2half2_rn(fA[2 * j], fA[2 * j + 1]);
                hp[j] = *(uint32_t*)&h;
            }
            const int off = ldRow * STRIDE + ldHalf * 32;
            *(uint4*)(st + off)      = *(uint4*)&hp[0];
            *(uint4*)(st + off + 16) = *(uint4*)&hp[4];
        }
    };
    auto loadB = [&](int kc, int s) {
        const uint32_t sdst = sbase + s * STAGE_B + B_H_OFF;
        #pragma unroll
        for (int u = 0; u < 4; u++) {
            int idx = tid + u * 256;          // 0..1023
            int row = idx >> 2, q = idx & 3;
            const __half* srcp = Bh + (size_t)row * 256 + kc * 32 + q * 8;
            cpasync16(sdst + row * STRIDE + q * 16, srcp);
        }
        if constexpr (!AF32) {
            const __half* A = (const __half*)Av;
            const uint32_t adst = sbase + s * STAGE_B;
            #pragma unroll
            for (int u = 0; u < 2; u++) {
                int idx = tid + u * 256;      // 0..511
                int row = idx >> 2, q = idx & 3;
                int grow = rowBlock + row;
                const __half* srcp = A + (size_t)(grow < M ? grow : M - 1) * 256 + kc * 32 + q * 8;
                cpasync16(adst + row * STRIDE + q * 16, srcp);
            }
        }
        CP_COMMIT();
    };

    // prologue
    loadA(0);
    loadB(0, 0);
    storeA(0);

    for (int kc = 0; kc < 8; kc++) {
        const int cur = kc & 1;
        CP_WAIT0();
        __syncthreads();
        if (kc < 7) { loadA(kc + 1); loadB(kc + 1, cur ^ 1); }

        const uint32_t sA = sbase + cur * STAGE_B;
        const uint32_t sB = sA + B_H_OFF;

        #pragma unroll
        for (int ks = 0; ks < 2; ks++) {
            uint32_t ah[4][4];
            const uint32_t arow = ((lane >> 3) & 1) * 8 + (lane & 7);
            const uint32_t akb  = ks * 32 + (lane >> 4) * 16;
            #pragma unroll
            for (int i = 0; i < 4; i++) {
                uint32_t addr = sA + (warpRow + i * 16 + arow) * STRIDE + akb;
                LDSM4(ah[i], addr);
            }
            const uint32_t brow = (lane >> 4) * 8 + (lane & 7);
            const uint32_t bkb  = ks * 32 + ((lane >> 3) & 1) * 16;
            #pragma unroll
            for (int jj = 0; jj < 4; jj++) {
                uint32_t bh[4];
                uint32_t addr = sB + (warpCol + jj * 16 + brow) * STRIDE + bkb;
                LDSM4(bh, addr);
                #pragma unroll
                for (int i = 0; i < 4; i++) {
                    mma_f16(acc[i][jj * 2],     ah[i], bh[0], bh[1]);
                    mma_f16(acc[i][jj * 2 + 1], ah[i], bh[2], bh[3]);
                }
            }
        }
        if (kc < 7) storeA(cur ^ 1);
    }

    // ---- epilogue: fp16 store + score projections via smem reduction ----
    __syncthreads();
    float* sS1 = (float*)smem;          // [128]
    float* sS2 = (float*)smem + 128;    // [128]
    if (tid < 128) { sS1[tid] = 0.f; sS2[tid] = 0.f; }
    __syncthreads();

    float a1x[8], a1y[8], a2x[8], a2y[8];
    #pragma unroll
    for (int j = 0; j < 8; j++) {
        const int c0 = warpCol + j * 8 + 2 * qcol;
        float2 p1 = *(const float2*)(avec + c0);
        float2 p2 = *(const float2*)(avec + 256 + c0);
        a1x[j] = p1.x; a1y[j] = p1.y;
        a2x[j] = p2.x; a2y[j] = p2.y;
    }
    #pragma unroll
    for (int i = 0; i < 4; i++) {
        const int lr0 = warpRow + i * 16 + qrow;
        const int lr1 = lr0 + 8;
        const int r0 = rowBlock + lr0, r1 = rowBlock + lr1;
        float s1_0 = 0.f, s2_0 = 0.f, s1_1 = 0.f, s2_1 = 0.f;
        #pragma unroll
        for (int j = 0; j < 8; j++) {
            const int c0 = warpCol + j * 8 + 2 * qcol;
            s1_0 += acc[i][j][0] * a1x[j] + acc[i][j][1] * a1y[j];
            s2_0 += acc[i][j][0] * a2x[j] + acc[i][j][1] * a2y[j];
            s1_1 += acc[i][j][2] * a1x[j] + acc[i][j][3] * a1y[j];
            s2_1 += acc[i][j][2] * a2x[j] + acc[i][j][3] * a2y[j];
            if (r0 < M) {
                __half2 h = __floats2half2_rn(acc[i][j][0], acc[i][j][1]);
                *(__half2*)(Chalf + (size_t)r0 * 256 + c0) = h;
            }
            if (r1 < M) {
                __half2 h = __floats2half2_rn(acc[i][j][2], acc[i][j][3]);
                *(__half2*)(Chalf + (size_t)r1 * 256 + c0) = h;
            }
        }
        #pragma unroll
        for (int off = 1; off < 4; off <<= 1) {
            s1_0 += __shfl_xor_sync(0xffffffffu, s1_0, off);
            s2_0 += __shfl_xor_sync(0xffffffffu, s2_0, off);
            s1_1 += __shfl_xor_sync(0xffffffffu, s1_1, off);
            s2_1 += __shfl_xor_sync(0xffffffffu, s2_1, off);
        }
        if (qcol == 0) {
            atomicAdd(&sS1[lr0], s1_0);
            atomicAdd(&sS2[lr0], s2_0);
            atomicAdd(&sS1[lr1], s1_1);
            atomicAdd(&sS2[lr1], s2_1);
        }
    }
    __syncthreads();
    if (tid < 128 && rowBlock + tid < M) {
        g_ssrc[rowBlock + tid] = sS1[tid];
        g_sdst[rowBlock + tid] = sS2[tid];
    }
}

// ---------------- edge aggregation: one warp per node, fp16 gather -----------
__device__ __forceinline__ float elu1(float x) {
    return x > 0.f ? x : (__expf(x) - 1.f);
}

template <typename OT>
__global__ __launch_bounds__(256) void agg_k(const __half* __restrict__ h2h,
                                             OT* __restrict__ out, int n) {
    int warp = (blockIdx.x * blockDim.x + threadIdx.x) >> 5;
    int lane = threadIdx.x & 31;
    if (warp >= n) return;
    const int start = g_rowptr[warp];
    const int end   = g_rowptr[warp + 1];
    const float s_i = g_ssrc[warp];

    float acc[8];
    #pragma unroll
    for (int t = 0; t < 8; t++) acc[t] = 0.f;
    float denom = 0.f;

    for (int j = start; j < end; j += 32) {
        int myj = j + lane;
        float e = 0.f;
        int d = 0;
        if (myj < end) {
            d = g_col[myj];
            float sc = s_i + g_sdst[d];
            float l  = sc > 0.f ? sc : 0.2f * sc;
            e = __expf(-l);
        }
        int cnt = end - j;
        if (cnt > 32) cnt = 32;
        #pragma unroll 4
        for (int k = 0; k < cnt; k++) {
            float ek = __shfl_sync(0xffffffffu, e, k);
            int   dk = __shfl_sync(0xffffffffu, d, k);
            uint4 v = ((const uint4*)(h2h + (size_t)dk * 256))[lane];
            float2 f0 = __half22float2(*(__half2*)&v.x);
            float2 f1 = __half22float2(*(__half2*)&v.y);
            float2 f2 = __half22float2(*(__half2*)&v.z);
            float2 f3 = __half22float2(*(__half2*)&v.w);
            acc[0] += ek * f0.x; acc[1] += ek * f0.y;
            acc[2] += ek * f1.x; acc[3] += ek * f1.y;
            acc[4] += ek * f2.x; acc[5] += ek * f2.y;
            acc[6] += ek * f3.x; acc[7] += ek * f3.y;
            denom += ek;
        }
    }
    float inv = denom > 0.f ? 1.0f / denom : 0.f;
    float o[8];
    #pragma unroll
    for (int t = 0; t < 8; t++) o[t] = elu1(acc[t] * inv);
    if constexpr (sizeof(OT) == 2) {
        uint32_t hb[4];
        #pragma unroll
        for (int t = 0; t < 4; t++) {
            __half2 h = __floats2half2_rn(o[2 * t], o[2 * t + 1]);
            hb[t] = *(uint32_t*)&h;
        }
        *(uint4*)((__half*)out + (size_t)warp * 256 + lane * 8) = *(uint4*)hb;
    } else {
        float4* orow = (float4*)((float*)out + (size_t)warp * 256 + lane * 8);
        orow[0] = *(float4*)&o[0];
        orow[1] = *(float4*)&o[4];
    }
}

// ---------------- launch -----------------------------------------------------
extern "C" void kernel_launch(void* const* d_in, const int* in_sizes, int n_in,
                              void* d_out, int out_size) {
    const float* emb  = (const float*)d_in[0];
    const float* W1   = (const float*)d_in[1];
    const float* a1   = (const float*)d_in[2];
    const float* W2   = (const float*)d_in[3];
    const float* a2   = (const float*)d_in[4];
    const int*   edges = (const int*)d_in[5];

    const int N = in_sizes[0] / DDIM;     // 100000
    const int E = in_sizes[5] / 2;        // 3300000
    const int* src = edges;
    const int* dst = edges + E;

    __half* h2h;   cudaGetSymbolAddress((void**)&h2h,   g_h2h);
    __half* hmidh; cudaGetSymbolAddress((void**)&hmidh, g_hmidh);
    __half *w1h, *w2h;
    cudaGetSymbolAddress((void**)&w1h, g_W1h);
    cudaGetSymbolAddress((void**)&w2h, g_W2h);
    float* out = (float*)d_out;

    cudaFuncSetAttribute(mmagemm_k<1>, cudaFuncAttributeMaxDynamicSharedMemorySize, GSMEM_B);
    cudaFuncSetAttribute(mmagemm_k<0>, cudaFuncAttributeMaxDynamicSharedMemorySize, GSMEM_B);

    const int TB = 256;
    const int gemm_grid = (N + 127) / 128;
    const int e4 = (E / 4 + TB - 1) / TB + 1;
    const int nscan = (N + 4095) / 4096;   // 25 (<=32 required by scanfix_k)

    // fork: CSR build + W2 prep on side stream; W1 prep + GEMM1 on main stream
    cudaStream_t s2;
    cudaEvent_t evFork, evJoin;
    cudaStreamCreateWithFlags(&s2, cudaStreamNonBlocking);
    cudaEventCreateWithFlags(&evFork, cudaEventDisableTiming);
    cudaEventCreateWithFlags(&evJoin, cudaEventDisableTiming);

    cudaEventRecord(evFork, 0);
    cudaStreamWaitEvent(s2, evFork, 0);

    // side stream: CSR build + W2 split (independent of GEMM1)
    zero_counts_k<<<(N + TB - 1) / TB, TB, 0, s2>>>(N);
    hist_k<<<e4, TB, 0, s2>>>(src, E);
    scan1_k<<<nscan, 1024, 0, s2>>>(N);
    scanfix_k<<<nscan, 1024, 0, s2>>>(N, nscan);
    scatter_k<<<e4, TB, 0, s2>>>(src, dst, E);
    wsplit_k<<<256, 256, 0, s2>>>(W2, w2h);
    cudaEventRecord(evJoin, s2);

    // main stream: W1 prep + layer-1 GEMM
    wsplit_k<<<256, 256>>>(W1, w1h);
    mmagemm_k<1><<<gemm_grid, TB, GSMEM_B>>>(emb, w1h, a1, h2h, N);

    // join: aggregation needs CSR + GEMM1
    cudaStreamWaitEvent(0, evJoin, 0);
    agg_k<__half><<<(N * 32 + TB - 1) / TB, TB>>>(h2h, hmidh, N);

    // layer 2 (A already fp16; W2 split done on side stream before join)
    mmagemm_k<0><<<gemm_grid, TB, GSMEM_B>>>(hmidh, w2h, a2, h2h, N);
    agg_k<float><<<(N * 32 + TB - 1) / TB, TB>>>(h2h, out, N);
}

// round 17
// speedup vs baseline: 1.0501x; 1.0318x over previous
#include <cuda_runtime.h>
#include <cuda_fp16.h>
#include <cuda_bf16.h>
#include <cstdint>

#define NNODE 100000
#define DDIM  256
#define EMAX  3400000

// ---------------- scratch (static device globals; no allocation) -------------
__device__ __half g_h2h  [(size_t)NNODE * DDIM];  // h @ W (fp16, gather source)
__device__ __half g_hmidh[(size_t)NNODE * DDIM];  // layer-1 output (fp16)
__device__ float  g_ssrc[NNODE];
__device__ float  g_sdst[NNODE];
__device__ int    g_counts[NNODE];
__device__ int    g_rowptr[NNODE + 1];
__device__ int    g_rank[EMAX];
__device__ int    g_col[EMAX];
__device__ int    g_bsum[64];
// W^T as fp16, per layer: [N=256][K=256]
__device__ __half g_W1h[65536];
__device__ __half g_W2h[65536];

// ---------------- helpers -----------------------------------------------------
__device__ __forceinline__ uint32_t smem_u32(const void* p) {
    uint32_t a;
    asm("{ .reg .u64 t; cvta.to.shared.u64 t, %1; cvt.u32.u64 %0, t; }" : "=r"(a) : "l"(p));
    return a;
}
__device__ __forceinline__ void cpasync16(uint32_t dst, const void* src) {
    asm volatile("cp.async.cg.shared.global [%0], [%1], 16;" :: "r"(dst), "l"(src));
}
#define CP_COMMIT() asm volatile("cp.async.commit_group;")
#define CP_WAIT0()  asm volatile("cp.async.wait_group 0;")
#define LDSM4(R, addr) \
    asm volatile("ldmatrix.sync.aligned.m8n8.x4.shared.b16 {%0,%1,%2,%3}, [%4];" \
                 : "=r"((R)[0]), "=r"((R)[1]), "=r"((R)[2]), "=r"((R)[3]) : "r"(addr))

__device__ __forceinline__ void mma_f16(float* c, const uint32_t* a,
                                        uint32_t b0, uint32_t b1) {
    asm volatile(
        "mma.sync.aligned.m16n8k16.row.col.f32.f16.f16.f32 "
        "{%0,%1,%2,%3}, {%4,%5,%6,%7}, {%8,%9}, {%0,%1,%2,%3};"
        : "+f"(c[0]), "+f"(c[1]), "+f"(c[2]), "+f"(c[3])
        : "r"(a[0]), "r"(a[1]), "r"(a[2]), "r"(a[3]), "r"(b0), "r"(b1));
}

// ---------------- CSR build --------------------------------------------------
__global__ void zero_counts_k(int n) {
    int i = blockIdx.x * blockDim.x + threadIdx.x;
    if (i < n) g_counts[i] = 0;
}

// histogram + per-edge rank (old count value)
__global__ void hist_k(const int* __restrict__ src, int E) {
    int i = (blockIdx.x * blockDim.x + threadIdx.x) * 4;
    if (i + 3 < E) {
        int4 s = *(const int4*)(src + i);
        int4 r;
        r.x = atomicAdd(&g_counts[s.x], 1);
        r.y = atomicAdd(&g_counts[s.y], 1);
        r.z = atomicAdd(&g_counts[s.z], 1);
        r.w = atomicAdd(&g_counts[s.w], 1);
        *(int4*)(g_rank + i) = r;
    } else {
        for (int q = i; q < E; q++) g_rank[q] = atomicAdd(&g_counts[src[q]], 1);
    }
}

// phase 1: per-block (4096 elems) exclusive scan into rowptr + block sums
__global__ void scan1_k(int n) {
    __shared__ int wsum[32];
    const int tid = threadIdx.x, lane = tid & 31, w = tid >> 5;
    const int i0 = blockIdx.x * 4096 + tid * 4;
    int v0 = 0, v1 = 0, v2 = 0, v3 = 0;
    if (i0 + 3 < n) {
        int4 t = *(const int4*)&g_counts[i0];
        v0 = t.x; v1 = t.y; v2 = t.z; v3 = t.w;
    } else {
        if (i0 + 0 < n) v0 = g_counts[i0 + 0];
        if (i0 + 1 < n) v1 = g_counts[i0 + 1];
        if (i0 + 2 < n) v2 = g_counts[i0 + 2];
        if (i0 + 3 < n) v3 = g_counts[i0 + 3];
    }
    int s0 = v0, s1 = s0 + v1, s2 = s1 + v2, s3 = s2 + v3;
    int incl = s3;
    #pragma unroll
    for (int off = 1; off < 32; off <<= 1) {
        int u = __shfl_up_sync(0xffffffffu, incl, off);
        if (lane >= off) incl += u;
    }
    if (lane == 31) wsum[w] = incl;
    __syncthreads();
    if (w == 0) {
        int x = wsum[lane], xi = x;
        #pragma unroll
        for (int off = 1; off < 32; off <<= 1) {
            int u = __shfl_up_sync(0xffffffffu, xi, off);
            if (lane >= off) xi += u;
        }
        if (lane == 31) g_bsum[blockIdx.x] = xi;
        wsum[lane] = xi - x;
    }
    __syncthreads();
    int eb = wsum[w] + (incl - s3);
    if (i0 + 0 < n) g_rowptr[i0 + 0] = eb;
    if (i0 + 1 < n) g_rowptr[i0 + 1] = eb + s0;
    if (i0 + 2 < n) g_rowptr[i0 + 2] = eb + s1;
    if (i0 + 3 < n) g_rowptr[i0 + 3] = eb + s2;
}

// phase 2: every block redundantly scans the <=32 block sums, adds its offset
__global__ void scanfix_k(int n, int nb) {
    __shared__ int soff[2];
    if (threadIdx.x < 32) {
        int lane = threadIdx.x;
        int v = (lane < nb) ? g_bsum[lane] : 0;
        int xi = v;
        #pragma unroll
        for (int off = 1; off < 32; off <<= 1) {
            int u = __shfl_up_sync(0xffffffffu, xi, off);
            if (lane >= off) xi += u;
        }
        if (lane == (int)blockIdx.x) soff[0] = xi - v;   // exclusive prefix of this block
        if (lane == nb - 1)          soff[1] = xi;       // grand total
    }
    __syncthreads();
    const int off = soff[0];
    const int i0 = blockIdx.x * 4096 + threadIdx.x * 4;
    #pragma unroll
    for (int q = 0; q < 4; q++) {
        int i = i0 + q;
        if (i < n) g_rowptr[i] += off;
    }
    if ((int)blockIdx.x == nb - 1 && threadIdx.x == 0) g_rowptr[n] = soff[1];
}

// atomic-free scatter: position = rowptr[src] + rank
__global__ void scatter_k(const int* __restrict__ src, const int* __restrict__ dst, int E) {
    int i = (blockIdx.x * blockDim.x + threadIdx.x) * 4;
    if (i + 3 < E) {
        int4 s = *(const int4*)(src + i);
        int4 d = *(const int4*)(dst + i);
        int4 r = *(const int4*)(g_rank + i);
        g_col[g_rowptr[s.x] + r.x] = d.x;
        g_col[g_rowptr[s.y] + r.y] = d.y;
        g_col[g_rowptr[s.z] + r.z] = d.z;
        g_col[g_rowptr[s.w] + r.w] = d.w;
    } else {
        for (int q = i; q < E; q++)
            g_col[g_rowptr[src[q]] + g_rank[q]] = dst[q];
    }
}

// ---------------- W transpose to fp16 ----------------------------------------
__global__ void wsplit_k(const float* __restrict__ W, __half* __restrict__ Wh) {
    int n = blockIdx.x, k = threadIdx.x;
    Wh[n * 256 + k] = __float2half_rn(W[k * 256 + n]);
}

// ---------------- HMMA fp16 GEMM (64x256 tile, 2 CTAs/SM) --------------------
// C[M,256] = A[M,256] @ W ; C = Ah*Bh, both fp16, fp32 accumulate.
// CTA 64x256, 8 warps (2m x 4n), warp tile 32x64, K chunk 32, double-buffered.
// 2 CTAs/SM co-residency hides cp.async wait + A-convert latency.
#define STRIDE  80
#define B_H_OFF 5120                    // A tile: 64 rows * 80 B
#define STAGE_B 25600                   // A 5120 + B 20480
#define GSMEM_B (2 * STAGE_B)           // 51200 per CTA

template <int AF32>
__global__ __launch_bounds__(256, 2) void mmagemm_k(const void* __restrict__ Av,
                                                    const __half* __restrict__ Bh,
                                                    const float* __restrict__ avec,
                                                    __half* __restrict__ Chalf, int M) {
    extern __shared__ char smem[];
    const uint32_t sbase = smem_u32(smem);
    const int tid = threadIdx.x;
    const int rowBlock = blockIdx.x * 64;
    const int wid = tid >> 5, lane = tid & 31;
    const int warpRow = (wid >> 2) * 32;   // 0 / 32
    const int warpCol = (wid & 3) * 64;    // 0..192
    const int qrow = lane >> 2, qcol = lane & 3;

    float acc[2][8][4];
    #pragma unroll
    for (int i = 0; i < 2; i++)
        #pragma unroll
        for (int j = 0; j < 8; j++)
            #pragma unroll
            for (int t = 0; t < 4; t++) acc[i][j][t] = 0.f;

    // A producer: 4 threads per row; thread covers fp32 elems [q8*8, q8*8+8)
    const int ldRow = tid >> 2, ldQ = tid & 3;
    const int aRowG = rowBlock + ldRow;
    float fA[8];

    auto loadA = [&](int kc) {
        if constexpr (AF32) {
            const float* A = (const float*)Av;
            if (aRowG < M) {
                const float4* ap = (const float4*)(A + (size_t)aRowG * 256 + kc * 32 + ldQ * 8);
                *(float4*)&fA[0] = ap[0];
                *(float4*)&fA[4] = ap[1];
            } else {
                #pragma unroll
                for (int q = 0; q < 8; q++) fA[q] = 0.f;
            }
        }
    };
    auto storeA = [&](int s) {
        if constexpr (AF32) {
            char* st = smem + s * STAGE_B;
            uint32_t hp[4];
            #pragma unroll
            for (int j = 0; j < 4; j++) {
                __half2 h = __floats2half2_rn(fA[2 * j], fA[2 * j + 1]);
                hp[j] = *(uint32_t*)&h;
            }
            *(uint4*)(st + ldRow * STRIDE + ldQ * 16) = *(uint4*)hp;
        }
    };
    auto loadB = [&](int kc, int s) {
        const uint32_t sdst = sbase + s * STAGE_B + B_H_OFF;
        #pragma unroll
        for (int u = 0; u < 4; u++) {
            int idx = tid + u * 256;          // 0..1023
            int row = idx >> 2, q = idx & 3;
            const __half* srcp = Bh + (size_t)row * 256 + kc * 32 + q * 8;
            cpasync16(sdst + row * STRIDE + q * 16, srcp);
        }
        if constexpr (!AF32) {
            const __half* A = (const __half*)Av;
            const uint32_t adst = sbase + s * STAGE_B;
            // 64 rows * 64 B = 256 x 16 B -> 1 per thread
            int grow = rowBlock + ldRow;
            const __half* srcp = A + (size_t)(grow < M ? grow : M - 1) * 256 + kc * 32 + ldQ * 8;
            cpasync16(adst + ldRow * STRIDE + ldQ * 16, srcp);
        }
        CP_COMMIT();
    };

    // prologue
    loadA(0);
    loadB(0, 0);
    storeA(0);

    for (int kc = 0; kc < 8; kc++) {
        const int cur = kc & 1;
        CP_WAIT0();
        __syncthreads();
        if (kc < 7) { loadA(kc + 1); loadB(kc + 1, cur ^ 1); }

        const uint32_t sA = sbase + cur * STAGE_B;
        const uint32_t sB = sA + B_H_OFF;

        #pragma unroll
        for (int ks = 0; ks < 2; ks++) {
            uint32_t ah[2][4];
            const uint32_t arow = ((lane >> 3) & 1) * 8 + (lane & 7);
            const uint32_t akb  = ks * 32 + (lane >> 4) * 16;
            #pragma unroll
            for (int i = 0; i < 2; i++) {
                uint32_t addr = sA + (warpRow + i * 16 + arow) * STRIDE + akb;
                LDSM4(ah[i], addr);
            }
            const uint32_t brow = (lane >> 4) * 8 + (lane & 7);
            const uint32_t bkb  = ks * 32 + ((lane >> 3) & 1) * 16;
            #pragma unroll
            for (int jj = 0; jj < 4; jj++) {
                uint32_t bh[4];
                uint32_t addr = sB + (warpCol + jj * 16 + brow) * STRIDE + bkb;
                LDSM4(bh, addr);
                #pragma unroll
                for (int i = 0; i < 2; i++) {
                    mma_f16(acc[i][jj * 2],     ah[i], bh[0], bh[1]);
                    mma_f16(acc[i][jj * 2 + 1], ah[i], bh[2], bh[3]);
                }
            }
        }
        if (kc < 7) storeA(cur ^ 1);
    }

    // ---- epilogue: fp16 store + score projections via smem reduction ----
    __syncthreads();
    float* sS1 = (float*)smem;          // [64]
    float* sS2 = (float*)smem + 64;     // [64]
    if (tid < 64) { sS1[tid] = 0.f; sS2[tid] = 0.f; }
    __syncthreads();

    float a1x[8], a1y[8], a2x[8], a2y[8];
    #pragma unroll
    for (int j = 0; j < 8; j++) {
        const int c0 = warpCol + j * 8 + 2 * qcol;
        float2 p1 = *(const float2*)(avec + c0);
        float2 p2 = *(const float2*)(avec + 256 + c0);
        a1x[j] = p1.x; a1y[j] = p1.y;
        a2x[j] = p2.x; a2y[j] = p2.y;
    }
    #pragma unroll
    for (int i = 0; i < 2; i++) {
        const int lr0 = warpRow + i * 16 + qrow;
        const int lr1 = lr0 + 8;
        const int r0 = rowBlock + lr0, r1 = rowBlock + lr1;
        float s1_0 = 0.f, s2_0 = 0.f, s1_1 = 0.f, s2_1 = 0.f;
        #pragma unroll
        for (int j = 0; j < 8; j++) {
            const int c0 = warpCol + j * 8 + 2 * qcol;
            s1_0 += acc[i][j][0] * a1x[j] + acc[i][j][1] * a1y[j];
            s2_0 += acc[i][j][0] * a2x[j] + acc[i][j][1] * a2y[j];
            s1_1 += acc[i][j][2] * a1x[j] + acc[i][j][3] * a1y[j];
            s2_1 += acc[i][j][2] * a2x[j] + acc[i][j][3] * a2y[j];
            if (r0 < M) {
                __half2 h = __floats2half2_rn(acc[i][j][0], acc[i][j][1]);
                *(__half2*)(Chalf + (size_t)r0 * 256 + c0) = h;
            }
            if (r1 < M) {
                __half2 h = __floats2half2_rn(acc[i][j][2], acc[i][j][3]);
                *(__half2*)(Chalf + (size_t)r1 * 256 + c0) = h;
            }
        }
        #pragma unroll
        for (int off = 1; off < 4; off <<= 1) {
            s1_0 += __shfl_xor_sync(0xffffffffu, s1_0, off);
            s2_0 += __shfl_xor_sync(0xffffffffu, s2_0, off);
            s1_1 += __shfl_xor_sync(0xffffffffu, s1_1, off);
            s2_1 += __shfl_xor_sync(0xffffffffu, s2_1, off);
        }
        if (qcol == 0) {
            atomicAdd(&sS1[lr0], s1_0);
            atomicAdd(&sS2[lr0], s2_0);
            atomicAdd(&sS1[lr1], s1_1);
            atomicAdd(&sS2[lr1], s2_1);
        }
    }
    __syncthreads();
    if (tid < 64 && rowBlock + tid < M) {
        g_ssrc[rowBlock + tid] = sS1[tid];
        g_sdst[rowBlock + tid] = sS2[tid];
    }
}

// ---------------- edge aggregation: one warp per node, fp16 gather -----------
__device__ __forceinline__ float elu1(float x) {
    return x > 0.f ? x : (__expf(x) - 1.f);
}

template <typename OT>
__global__ __launch_bounds__(256) void agg_k(const __half* __restrict__ h2h,
                                             OT* __restrict__ out, int n) {
    int warp = (blockIdx.x * blockDim.x + threadIdx.x) >> 5;
    int lane = threadIdx.x & 31;
    if (warp >= n) return;
    const int start = g_rowptr[warp];
    const int end   = g_rowptr[warp + 1];
    const float s_i = g_ssrc[warp];

    float acc[8];
    #pragma unroll
    for (int t = 0; t < 8; t++) acc[t] = 0.f;
    float denom = 0.f;

    for (int j = start; j < end; j += 32) {
        int myj = j + lane;
        float e = 0.f;
        int d = 0;
        if (myj < end) {
            d = g_col[myj];
            float sc = s_i + g_sdst[d];
            float l  = sc > 0.f ? sc : 0.2f * sc;
            e = __expf(-l);
        }
        int cnt = end - j;
        if (cnt > 32) cnt = 32;
        #pragma unroll 4
        for (int k = 0; k < cnt; k++) {
            float ek = __shfl_sync(0xffffffffu, e, k);
            int   dk = __shfl_sync(0xffffffffu, d, k);
            uint4 v = ((const uint4*)(h2h + (size_t)dk * 256))[lane];
            float2 f0 = __half22float2(*(__half2*)&v.x);
            float2 f1 = __half22float2(*(__half2*)&v.y);
            float2 f2 = __half22float2(*(__half2*)&v.z);
            float2 f3 = __half22float2(*(__half2*)&v.w);
            acc[0] += ek * f0.x; acc[1] += ek * f0.y;
            acc[2] += ek * f1.x; acc[3] += ek * f1.y;
            acc[4] += ek * f2.x; acc[5] += ek * f2.y;
            acc[6] += ek * f3.x; acc[7] += ek * f3.y;
            denom += ek;
        }
    }
    float inv = denom > 0.f ? 1.0f / denom : 0.f;
    float o[8];
    #pragma unroll
    for (int t = 0; t < 8; t++) o[t] = elu1(acc[t] * inv);
    if constexpr (sizeof(OT) == 2) {
        uint32_t hb[4];
        #pragma unroll
        for (int t = 0; t < 4; t++) {
            __half2 h = __floats2half2_rn(o[2 * t], o[2 * t + 1]);
            hb[t] = *(uint32_t*)&h;
        }
        *(uint4*)((__half*)out + (size_t)warp * 256 + lane * 8) = *(uint4*)hb;
    } else {
        float4* orow = (float4*)((float*)out + (size_t)warp * 256 + lane * 8);
        orow[0] = *(float4*)&o[0];
        orow[1] = *(float4*)&o[4];
    }
}

// ---------------- launch -----------------------------------------------------
extern "C" void kernel_launch(void* const* d_in, const int* in_sizes, int n_in,
                              void* d_out, int out_size) {
    const float* emb  = (const float*)d_in[0];
    const float* W1   = (const float*)d_in[1];
    const float* a1   = (const float*)d_in[2];
    const float* W2   = (const float*)d_in[3];
    const float* a2   = (const float*)d_in[4];
    const int*   edges = (const int*)d_in[5];

    const int N = in_sizes[0] / DDIM;     // 100000
    const int E = in_sizes[5] / 2;        // 3300000
    const int* src = edges;
    const int* dst = edges + E;

    __half* h2h;   cudaGetSymbolAddress((void**)&h2h,   g_h2h);
    __half* hmidh; cudaGetSymbolAddress((void**)&hmidh, g_hmidh);
    __half *w1h, *w2h;
    cudaGetSymbolAddress((void**)&w1h, g_W1h);
    cudaGetSymbolAddress((void**)&w2h, g_W2h);
    float* out = (float*)d_out;

    cudaFuncSetAttribute(mmagemm_k<1>, cudaFuncAttributeMaxDynamicSharedMemorySize, GSMEM_B);
    cudaFuncSetAttribute(mmagemm_k<0>, cudaFuncAttributeMaxDynamicSharedMemorySize, GSMEM_B);

    const int TB = 256;
    const int gemm_grid = (N + 63) / 64;
    const int e4 = (E / 4 + TB - 1) / TB + 1;
    const int nscan = (N + 4095) / 4096;   // 25 (<=32 required by scanfix_k)

    // fork: CSR build + W2 prep on side stream; W1 prep + GEMM1 on main stream
    cudaStream_t s2;
    cudaEvent_t evFork, evJoin;
    cudaStreamCreateWithFlags(&s2, cudaStreamNonBlocking);
    cudaEventCreateWithFlags(&evFork, cudaEventDisableTiming);
    cudaEventCreateWithFlags(&evJoin, cudaEventDisableTiming);

    cudaEventRecord(evFork, 0);
    cudaStreamWaitEvent(s2, evFork, 0);

    // side stream: CSR build + W2 split (independent of GEMM1)
    zero_counts_k<<<(N + TB - 1) / TB, TB, 0, s2>>>(N);
    hist_k<<<e4, TB, 0, s2>>>(src, E);
    scan1_k<<<nscan, 1024, 0, s2>>>(N);
    scanfix_k<<<nscan, 1024, 0, s2>>>(N, nscan);
    scatter_k<<<e4, TB, 0, s2>>>(src, dst, E);
    wsplit_k<<<256, 256, 0, s2>>>(W2, w2h);
    cudaEventRecord(evJoin, s2);

    // main stream: W1 prep + layer-1 GEMM
    wsplit_k<<<256, 256>>>(W1, w1h);
    mmagemm_k<1><<<gemm_grid, TB, GSMEM_B>>>(emb, w1h, a1, h2h, N);

    // join: aggregation needs CSR + GEMM1
    cudaStreamWaitEvent(0, evJoin, 0);
    agg_k<__half><<<(N * 32 + TB - 1) / TB, TB>>>(h2h, hmidh, N);

    // layer 2 (A already fp16; W2 split done on side stream before join)
    mmagemm_k<0><<<gemm_grid, TB, GSMEM_B>>>(hmidh, w2h, a2, h2h, N);
    agg_k<float><<<(N * 32 + TB - 1) / TB, TB>>>(h2h, out, N);
}